// round 13
// baseline (speedup 1.0000x reference)
#include <cuda_runtime.h>
#include <cuda_bf16.h>
#include <math.h>
#include <stdint.h>

#define NN 100000
#define EE 1600000
#define ENN (EE + NN)
#define NB_BN 391      /* ceil(NN/256) */
#define NB_LOSS 12500
#define NB_SCAN 98
#define GX 782         /* ceil(NN/128) */

// ---------------- static scratch ----------------
__device__ float g_h0s[NN * 128];
__device__ float g_h1s[NN * 128];
__device__ float g_h0t[NN * 128];
__device__ float g_h1t[NN * 128];
__device__ float g_teach0[NN * 128];
__device__ float g_teach1[NN * 128];
__device__ float g_pred0[NN * 128];
__device__ float g_pred1[NN * 128];

__device__ __nv_bfloat16 g_ahi[(size_t)NN * 256];
__device__ __nv_bfloat16 g_alo[(size_t)NN * 256];
__device__ __nv_bfloat16 g_qhi[(size_t)NN * 512];
__device__ __nv_bfloat16 g_qlo[(size_t)NN * 512];
__device__ __nv_bfloat16 g_thi[NN * 128];
__device__ __nv_bfloat16 g_tlo[NN * 128];
__device__ __nv_bfloat16 g_wthi[65536];
__device__ __nv_bfloat16 g_wtlo[65536];

__device__ int   g_cnt[2 * NN];
__device__ float g_dinv[2 * NN];
__device__ int   g_rowptr[2 * (NN + 1)];
__device__ int   g_cursor[2 * NN];
__device__ int   g_col[2 * ENN];
__device__ float g_wgt[2 * ENN];
__device__ int   g_scan_incl[NN];
__device__ int   g_scan_bsum[NB_SCAN];

__device__ float g_psum[NB_BN * 128];
__device__ float g_psq[NB_BN * 128];
__device__ float g_scale[128];
__device__ float g_shift[128];
__device__ float g_losspart[NB_LOSS];

// ---------------- mma / ldmatrix helpers ----------------
__device__ __forceinline__ void mma_bf16(float* c, const uint32_t* a, const uint32_t* b) {
    asm volatile(
        "mma.sync.aligned.m16n8k16.row.col.f32.bf16.bf16.f32 "
        "{%0,%1,%2,%3},{%4,%5,%6,%7},{%8,%9},{%0,%1,%2,%3};"
        : "+f"(c[0]), "+f"(c[1]), "+f"(c[2]), "+f"(c[3])
        : "r"(a[0]), "r"(a[1]), "r"(a[2]), "r"(a[3]), "r"(b[0]), "r"(b[1]));
}
#define LDSM_X4(r0, r1, r2, r3, addr) \
    asm volatile("ldmatrix.sync.aligned.m8n8.x4.shared.b16 {%0,%1,%2,%3}, [%4];" \
                 : "=r"(r0), "=r"(r1), "=r"(r2), "=r"(r3) : "r"(addr))

// ---------------- prep kernels ----------------
__global__ void k_prep_a(const float* __restrict__ A, __nv_bfloat16* __restrict__ Ah,
                         __nv_bfloat16* __restrict__ Al, int total4) {
    int i = blockIdx.x * 256 + threadIdx.x;
    if (i >= total4) return;
    float4 v = ((const float4*)A)[i];
    float vs[4] = {v.x, v.y, v.z, v.w};
    __nv_bfloat16 h[4], l[4];
#pragma unroll
    for (int e = 0; e < 4; e++) {
        h[e] = __float2bfloat16(vs[e]);
        l[e] = __float2bfloat16(vs[e] - __bfloat162float(h[e]));
    }
    ((uint2*)Ah)[i] = *(uint2*)h;
    ((uint2*)Al)[i] = *(uint2*)l;
}

__global__ void k_prep_w(const float* __restrict__ W, __nv_bfloat16* __restrict__ Wh,
                         __nv_bfloat16* __restrict__ Wl, int K, int Mt) {
    int idx = blockIdx.x * 256 + threadIdx.x;
    if (idx >= K * Mt) return;
    int m = idx / K, k = idx - m * K;
    float v = W[(size_t)k * Mt + m];
    __nv_bfloat16 h = __float2bfloat16(v);
    Wh[idx] = h;
    Wl[idx] = __float2bfloat16(v - __bfloat162float(h));
}

// ---------------- bf16-split tensor GEMM, ldmatrix fragments ----------------
// C[n,Mt] = A[n,K] @ W[K,Mt]. A pre-split bf16 hi/lo [n][K]; W pre-split [Mt][K].
// CTA 128x128, 8 warps (2m x 4n), warp tile 64x32, KC=32 chunks, 3-term MMA.
#define KC 32
#define STR 40

__global__ __launch_bounds__(256) void k_bf_gemm(
    const __nv_bfloat16* __restrict__ Ahg, const __nv_bfloat16* __restrict__ Alg,
    const __nv_bfloat16* __restrict__ Wh, const __nv_bfloat16* __restrict__ Wl,
    const float* __restrict__ bias, const float* __restrict__ aprelu,
    float* __restrict__ C0, float* __restrict__ C1,
    __nv_bfloat16* __restrict__ Chi, __nv_bfloat16* __restrict__ Clo,
    int n, int K, int Mt) {
    __shared__ __nv_bfloat16 smh[4 * 128 * STR];
    const uint32_t sb = (uint32_t)__cvta_generic_to_shared(smh);
    const uint32_t OFF_AL = 128 * STR * 2, OFF_BH = 2 * 128 * STR * 2, OFF_BL = 3 * 128 * STR * 2;

    const int tid = threadIdx.x, lane = tid & 31, wid = tid >> 5;
    const int wm = wid & 1, wn = wid >> 1;
    const int bm = blockIdx.x * 128, bn = blockIdx.y * 128;
    const int lg = lane >> 2, lt = lane & 3;
    const int quad = lane >> 3, lrow = lane & 7;
    const int rowq = (quad & 1) * 8 + lrow;
    const int kq = (quad >> 1) * 8;

    float acc[4][4][4];
#pragma unroll
    for (int i = 0; i < 4; i++)
#pragma unroll
        for (int j = 0; j < 4; j++)
#pragma unroll
            for (int k = 0; k < 4; k++) acc[i][j][k] = 0.f;

    // ldmatrix base addresses (bytes into smem)
    uint32_t a_ad[4], b_ad[2];
#pragma unroll
    for (int mf = 0; mf < 4; mf++)
        a_ad[mf] = sb + (uint32_t)(((wm * 64 + mf * 16 + rowq) * STR + kq) * 2);
#pragma unroll
    for (int p = 0; p < 2; p++)
        b_ad[p] = sb + OFF_BH + (uint32_t)(((wn * 32 + p * 16 + rowq) * STR + kq) * 2);

    const int srow = tid & 127;           // staging row
    const int sks = (tid >> 7) * 16;      // k-half (16 halfs)
    const uint32_t st_a = sb + (uint32_t)((srow * STR + sks) * 2);
    const uint32_t st_b = st_a + OFF_BH;

    for (int k0 = 0; k0 < K; k0 += KC) {
        // stage A hi/lo
        {
            int gr = bm + srow;
            uint4 vh = make_uint4(0, 0, 0, 0), vl = vh, vh2 = vh, vl2 = vh;
            if (gr < n) {
                const uint4* ph = (const uint4*)(Ahg + (size_t)gr * K + k0 + sks);
                const uint4* pl = (const uint4*)(Alg + (size_t)gr * K + k0 + sks);
                vh = ph[0]; vh2 = ph[1];
                vl = pl[0]; vl2 = pl[1];
            }
            asm volatile("st.shared.v4.b32 [%0], {%1,%2,%3,%4};" :: "r"(st_a), "r"(vh.x), "r"(vh.y), "r"(vh.z), "r"(vh.w));
            asm volatile("st.shared.v4.b32 [%0], {%1,%2,%3,%4};" :: "r"(st_a + 16), "r"(vh2.x), "r"(vh2.y), "r"(vh2.z), "r"(vh2.w));
            asm volatile("st.shared.v4.b32 [%0], {%1,%2,%3,%4};" :: "r"(st_a + OFF_AL), "r"(vl.x), "r"(vl.y), "r"(vl.z), "r"(vl.w));
            asm volatile("st.shared.v4.b32 [%0], {%1,%2,%3,%4};" :: "r"(st_a + OFF_AL + 16), "r"(vl2.x), "r"(vl2.y), "r"(vl2.z), "r"(vl2.w));
        }
        // stage B hi/lo (rows always valid: Mt multiple of 128)
        {
            const uint4* ph = (const uint4*)(Wh + (size_t)(bn + srow) * K + k0 + sks);
            const uint4* pl = (const uint4*)(Wl + (size_t)(bn + srow) * K + k0 + sks);
            uint4 vh = ph[0], vh2 = ph[1], vl = pl[0], vl2 = pl[1];
            asm volatile("st.shared.v4.b32 [%0], {%1,%2,%3,%4};" :: "r"(st_b), "r"(vh.x), "r"(vh.y), "r"(vh.z), "r"(vh.w));
            asm volatile("st.shared.v4.b32 [%0], {%1,%2,%3,%4};" :: "r"(st_b + 16), "r"(vh2.x), "r"(vh2.y), "r"(vh2.z), "r"(vh2.w));
            asm volatile("st.shared.v4.b32 [%0], {%1,%2,%3,%4};" :: "r"(st_b + (OFF_BL - OFF_BH)), "r"(vl.x), "r"(vl.y), "r"(vl.z), "r"(vl.w));
            asm volatile("st.shared.v4.b32 [%0], {%1,%2,%3,%4};" :: "r"(st_b + (OFF_BL - OFF_BH) + 16), "r"(vl2.x), "r"(vl2.y), "r"(vl2.z), "r"(vl2.w));
        }
        __syncthreads();
#pragma unroll
        for (int kk = 0; kk < KC; kk += 16) {
            const uint32_t kb = kk * 2;
            uint32_t ah[4][4], al[4][4], bh[4][2], bl[4][2];
#pragma unroll
            for (int mf = 0; mf < 4; mf++) {
                LDSM_X4(ah[mf][0], ah[mf][1], ah[mf][2], ah[mf][3], a_ad[mf] + kb);
                LDSM_X4(al[mf][0], al[mf][1], al[mf][2], al[mf][3], a_ad[mf] + kb + OFF_AL);
            }
            // B matrices arrive as {n0-7/k0-7, n8-15/k0-7, n0-7/k8-15, n8-15/k8-15}:
            // route m1 -> b[2p+1][0] and m2 -> b[2p][1]
#pragma unroll
            for (int p = 0; p < 2; p++) {
                LDSM_X4(bh[2 * p][0], bh[2 * p + 1][0], bh[2 * p][1], bh[2 * p + 1][1], b_ad[p] + kb);
                LDSM_X4(bl[2 * p][0], bl[2 * p + 1][0], bl[2 * p][1], bl[2 * p + 1][1], b_ad[p] + kb + (OFF_BL - OFF_BH));
            }
#pragma unroll
            for (int mf = 0; mf < 4; mf++)
#pragma unroll
                for (int nf = 0; nf < 4; nf++) {
                    mma_bf16(acc[mf][nf], ah[mf], bh[nf]);
                    mma_bf16(acc[mf][nf], ah[mf], bl[nf]);
                    mma_bf16(acc[mf][nf], al[mf], bh[nf]);
                }
        }
        __syncthreads();
    }

    // epilogue
    float alv = aprelu ? __ldg(aprelu) : 0.f;
#pragma unroll
    for (int mf = 0; mf < 4; mf++) {
        int r0 = bm + wm * 64 + mf * 16 + lg;
#pragma unroll
        for (int nf = 0; nf < 4; nf++) {
            int gcg = bn + wn * 32 + nf * 8 + lt * 2;
            float2 v0 = make_float2(acc[mf][nf][0], acc[mf][nf][1]);
            float2 v1 = make_float2(acc[mf][nf][2], acc[mf][nf][3]);
            if (bias) {
                float b0 = __ldg(&bias[gcg]), b1 = __ldg(&bias[gcg + 1]);
                v0.x += b0; v0.y += b1; v1.x += b0; v1.y += b1;
            }
            if (aprelu) {
                v0.x = v0.x >= 0.f ? v0.x : alv * v0.x;
                v0.y = v0.y >= 0.f ? v0.y : alv * v0.y;
                v1.x = v1.x >= 0.f ? v1.x : alv * v1.x;
                v1.y = v1.y >= 0.f ? v1.y : alv * v1.y;
            }
            if (Chi) {
                // bf16 hi/lo split output, stride Mt
                if (r0 < n) {
                    __nv_bfloat16 h0 = __float2bfloat16(v0.x), h1 = __float2bfloat16(v0.y);
                    __nv_bfloat16 l0 = __float2bfloat16(v0.x - __bfloat162float(h0));
                    __nv_bfloat16 l1 = __float2bfloat16(v0.y - __bfloat162float(h1));
                    __nv_bfloat16 hp[2] = {h0, h1}, lp[2] = {l0, l1};
                    *(uint32_t*)(Chi + (size_t)r0 * Mt + gcg) = *(uint32_t*)hp;
                    *(uint32_t*)(Clo + (size_t)r0 * Mt + gcg) = *(uint32_t*)lp;
                }
                if (r0 + 8 < n) {
                    __nv_bfloat16 h0 = __float2bfloat16(v1.x), h1 = __float2bfloat16(v1.y);
                    __nv_bfloat16 l0 = __float2bfloat16(v1.x - __bfloat162float(h0));
                    __nv_bfloat16 l1 = __float2bfloat16(v1.y - __bfloat162float(h1));
                    __nv_bfloat16 hp[2] = {h0, h1}, lp[2] = {l0, l1};
                    *(uint32_t*)(Chi + (size_t)(r0 + 8) * Mt + gcg) = *(uint32_t*)hp;
                    *(uint32_t*)(Clo + (size_t)(r0 + 8) * Mt + gcg) = *(uint32_t*)lp;
                }
            } else {
                float* Cd;
                int col, cstr;
                if (C1) { Cd = (gcg < 128) ? C0 : C1; col = gcg & 127; cstr = 128; }
                else { Cd = C0; col = gcg; cstr = Mt; }
                if (r0 < n) *(float2*)(Cd + (size_t)r0 * cstr + col) = v0;
                if (r0 + 8 < n) *(float2*)(Cd + (size_t)(r0 + 8) * cstr + col) = v1;
            }
        }
    }
}

// ---------------- CSR build ----------------
__global__ void k_init_cnt(int* cnt) {
    int i = blockIdx.x * 256 + threadIdx.x;
    if (i < NN) cnt[i] = 1;
}
__global__ void k_count(const int* __restrict__ ei, int* cnt) {
    int e = blockIdx.x * 256 + threadIdx.x;
    if (e < EE) atomicAdd(&cnt[ei[EE + e]], 1);
}
__global__ void k_dinv(const int* __restrict__ cnt, float* dinv) {
    int i = blockIdx.x * 256 + threadIdx.x;
    if (i < NN) dinv[i] = rsqrtf((float)cnt[i]);
}
__global__ void k_scan_block(const int* __restrict__ cnt, int* incl, int* bsum) {
    __shared__ int sm[1024];
    int i = blockIdx.x * 1024 + threadIdx.x;
    int v = (i < NN) ? cnt[i] : 0;
    sm[threadIdx.x] = v;
    __syncthreads();
    for (int off = 1; off < 1024; off <<= 1) {
        int t = (threadIdx.x >= off) ? sm[threadIdx.x - off] : 0;
        __syncthreads();
        sm[threadIdx.x] += t;
        __syncthreads();
    }
    if (i < NN) incl[i] = sm[threadIdx.x];
    if (threadIdx.x == 1023) bsum[blockIdx.x] = sm[1023];
}
__global__ void k_scan_sums(int* bsum) {
    if (threadIdx.x == 0 && blockIdx.x == 0) {
        int acc = 0;
        for (int b = 0; b < NB_SCAN; b++) { int t = bsum[b]; bsum[b] = acc; acc += t; }
    }
}
__global__ void k_finalize_rowptr(const int* __restrict__ cnt, const int* __restrict__ incl,
                                  const int* __restrict__ bsum, int* rowptr, int* cursor) {
    int i = blockIdx.x * 256 + threadIdx.x;
    if (i < NN) {
        int inclg = incl[i] + bsum[i >> 10];
        int excl = inclg - cnt[i];
        rowptr[i] = excl;
        cursor[i] = excl;
        if (i == NN - 1) rowptr[NN] = inclg;
    }
}
__global__ void k_fill(const int* __restrict__ ei, const float* __restrict__ dinv,
                       int* cursor, int* col, float* wgt) {
    int t = blockIdx.x * 256 + threadIdx.x;
    if (t < EE) {
        int s = ei[t], d = ei[EE + t];
        int p = atomicAdd(&cursor[d], 1);
        col[p] = s;
        wgt[p] = dinv[s] * dinv[d];
    } else if (t < ENN) {
        int i = t - EE;
        int p = atomicAdd(&cursor[i], 1);
        col[p] = i;
        wgt[p] = dinv[i] * dinv[i];
    }
}

// ---------------- propagate ----------------
__global__ __launch_bounds__(256) void k_prop(const int* __restrict__ rowptr,
                                              const int* __restrict__ col,
                                              const float* __restrict__ wgt,
                                              const float* __restrict__ h,
                                              const float* __restrict__ bias,
                                              float* __restrict__ out) {
    int w = (blockIdx.x * 256 + threadIdx.x) >> 5;
    int lane = threadIdx.x & 31;
    if (w >= NN) return;
    int beg = rowptr[w], end = rowptr[w + 1];
    float4 acc = make_float4(0.f, 0.f, 0.f, 0.f);
    const float4* H = (const float4*)h;
    for (int e = beg; e < end; e++) {
        int s = __ldg(&col[e]);
        float wv = __ldg(&wgt[e]);
        float4 v = __ldg(&H[(size_t)s * 32 + lane]);
        acc.x = fmaf(wv, v.x, acc.x);
        acc.y = fmaf(wv, v.y, acc.y);
        acc.z = fmaf(wv, v.z, acc.z);
        acc.w = fmaf(wv, v.w, acc.w);
    }
    float4 b = ((const float4*)bias)[lane];
    acc.x += b.x; acc.y += b.y; acc.z += b.z; acc.w += b.w;
    ((float4*)out)[(size_t)w * 32 + lane] = acc;
}

// ---------------- BN ----------------
__global__ __launch_bounds__(256) void k_bn_stats(const float* __restrict__ x,
                                                  float* __restrict__ psum,
                                                  float* __restrict__ psq) {
    __shared__ float4 smS[256], smQ[256];
    int t = threadIdx.x;
    int cg = t & 31, rr = t >> 5;
    int rowStart = blockIdx.x * 256;
    int rowEnd = rowStart + 256; if (rowEnd > NN) rowEnd = NN;
    float4 s = make_float4(0.f, 0.f, 0.f, 0.f), q = s;
    const float4* X = (const float4*)x;
    for (int r = rowStart + rr; r < rowEnd; r += 8) {
        float4 v = X[(size_t)r * 32 + cg];
        s.x += v.x; s.y += v.y; s.z += v.z; s.w += v.w;
        q.x = fmaf(v.x, v.x, q.x); q.y = fmaf(v.y, v.y, q.y);
        q.z = fmaf(v.z, v.z, q.z); q.w = fmaf(v.w, v.w, q.w);
    }
    smS[t] = s; smQ[t] = q;
    __syncthreads();
    if (rr == 0) {
        for (int k = 1; k < 8; k++) {
            float4 a = smS[k * 32 + cg], b = smQ[k * 32 + cg];
            s.x += a.x; s.y += a.y; s.z += a.z; s.w += a.w;
            q.x += b.x; q.y += b.y; q.z += b.z; q.w += b.w;
        }
        ((float4*)psum)[blockIdx.x * 32 + cg] = s;
        ((float4*)psq)[blockIdx.x * 32 + cg] = q;
    }
}
__global__ void k_bn_fin(const float* __restrict__ psum, const float* __restrict__ psq,
                         const float* __restrict__ g, const float* __restrict__ be,
                         float* scale, float* shift) {
    int c = threadIdx.x;
    float s = 0.f, q = 0.f;
    for (int b = 0; b < NB_BN; b++) { s += psum[b * 128 + c]; q += psq[b * 128 + c]; }
    float mu = s / (float)NN;
    float var = q / (float)NN - mu * mu;
    var = fmaxf(var, 0.f);
    float inv = rsqrtf(var + 1e-5f);
    float sc = g[c] * inv;
    scale[c] = sc;
    shift[c] = be[c] - mu * sc;
}
// bn_apply: fp32 out (optional) + bf16 hi/lo split out (optional)
__global__ __launch_bounds__(256) void k_bn_apply(const float* __restrict__ x,
                                                  const float* __restrict__ scale,
                                                  const float* __restrict__ shift,
                                                  const float* __restrict__ aptr,
                                                  float* __restrict__ out,
                                                  __nv_bfloat16* __restrict__ hi,
                                                  __nv_bfloat16* __restrict__ lo) {
    int i = blockIdx.x * 256 + threadIdx.x;
    if (i >= NN * 32) return;
    int cg = i & 31;
    float a = *aptr;
    float4 v = ((const float4*)x)[i];
    float4 sc = ((const float4*)scale)[cg];
    float4 sh = ((const float4*)shift)[cg];
    v.x = fmaf(v.x, sc.x, sh.x); v.y = fmaf(v.y, sc.y, sh.y);
    v.z = fmaf(v.z, sc.z, sh.z); v.w = fmaf(v.w, sc.w, sh.w);
    v.x = v.x >= 0.f ? v.x : a * v.x;
    v.y = v.y >= 0.f ? v.y : a * v.y;
    v.z = v.z >= 0.f ? v.z : a * v.z;
    v.w = v.w >= 0.f ? v.w : a * v.w;
    if (out) ((float4*)out)[i] = v;
    if (hi) {
        float vs[4] = {v.x, v.y, v.z, v.w};
        __nv_bfloat16 h[4], l[4];
#pragma unroll
        for (int e = 0; e < 4; e++) {
            h[e] = __float2bfloat16(vs[e]);
            l[e] = __float2bfloat16(vs[e] - __bfloat162float(h[e]));
        }
        ((uint2*)hi)[i] = *(uint2*)h;
        ((uint2*)lo)[i] = *(uint2*)l;
    }
}

// ---------------- loss ----------------
__global__ __launch_bounds__(256) void k_loss(const float4* __restrict__ p1,
                                              const float4* __restrict__ t2,
                                              const float4* __restrict__ p2,
                                              const float4* __restrict__ t1,
                                              float* __restrict__ part) {
    int w = (blockIdx.x * 256 + threadIdx.x) >> 5;
    int lane = threadIdx.x & 31;
    float contrib = 0.f;
    if (w < NN) {
        float4 a = p1[(size_t)w * 32 + lane];
        float4 b = t2[(size_t)w * 32 + lane];
        float4 c = p2[(size_t)w * 32 + lane];
        float4 d = t1[(size_t)w * 32 + lane];
        float dab = a.x * b.x + a.y * b.y + a.z * b.z + a.w * b.w;
        float naa = a.x * a.x + a.y * a.y + a.z * a.z + a.w * a.w;
        float nbb = b.x * b.x + b.y * b.y + b.z * b.z + b.w * b.w;
        float dcd = c.x * d.x + c.y * d.y + c.z * d.z + c.w * d.w;
        float ncc = c.x * c.x + c.y * c.y + c.z * c.z + c.w * c.w;
        float ndd = d.x * d.x + d.y * d.y + d.z * d.z + d.w * d.w;
        for (int off = 16; off; off >>= 1) {
            dab += __shfl_xor_sync(0xffffffffu, dab, off);
            naa += __shfl_xor_sync(0xffffffffu, naa, off);
            nbb += __shfl_xor_sync(0xffffffffu, nbb, off);
            dcd += __shfl_xor_sync(0xffffffffu, dcd, off);
            ncc += __shfl_xor_sync(0xffffffffu, ncc, off);
            ndd += __shfl_xor_sync(0xffffffffu, ndd, off);
        }
        if (lane == 0) {
            float c1 = dab / (fmaxf(sqrtf(naa), 1e-12f) * fmaxf(sqrtf(nbb), 1e-12f));
            float c2 = dcd / (fmaxf(sqrtf(ncc), 1e-12f) * fmaxf(sqrtf(ndd), 1e-12f));
            contrib = 4.f - 2.f * c1 - 2.f * c2;
        }
    }
    __shared__ float sm[8];
    int wl = threadIdx.x >> 5;
    if (lane == 0) sm[wl] = contrib;
    __syncthreads();
    if (threadIdx.x == 0) {
        float s = 0.f;
        for (int i = 0; i < 8; i++) s += sm[i];
        part[blockIdx.x] = s;
    }
}
__global__ void k_loss_fin(const float* __restrict__ part, float* __restrict__ outp) {
    __shared__ float sm[256];
    float s = 0.f;
    for (int i = threadIdx.x; i < NB_LOSS; i += 256) s += part[i];
    sm[threadIdx.x] = s;
    __syncthreads();
    for (int off = 128; off; off >>= 1) {
        if (threadIdx.x < off) sm[threadIdx.x] += sm[threadIdx.x + off];
        __syncthreads();
    }
    if (threadIdx.x == 0) outp[0] = sm[0] / (float)NN;
}

// ---------------- host orchestration ----------------
extern "C" void kernel_launch(void* const* d_in, const int* in_sizes, int n_in,
                              void* d_out, int out_size) {
    (void)in_sizes; (void)n_in; (void)out_size;
    const float* x1 = (const float*)d_in[0];
    const float* x2 = (const float*)d_in[1];
    const int* ei1 = (const int*)d_in[2];
    const int* ei2 = (const int*)d_in[3];
    const float* sp[10]; for (int i = 0; i < 10; i++) sp[i] = (const float*)d_in[4 + i];
    const float* tp[10]; for (int i = 0; i < 10; i++) tp[i] = (const float*)d_in[14 + i];
    const float* pW1 = (const float*)d_in[24];
    const float* pb1 = (const float*)d_in[25];
    const float* pa  = (const float*)d_in[26];
    const float* pW2 = (const float*)d_in[27];
    const float* pb2 = (const float*)d_in[28];
    float* out = (float*)d_out;

    float *h0s, *h1s, *h0t, *h1t, *teach0, *teach1, *pred0, *pred1;
    float *dinvB, *wgtB, *psum, *psq, *scale, *shift, *losspart;
    __nv_bfloat16 *ahi, *alo, *qhi, *qlo, *thi, *tlo, *wthi, *wtlo;
    int *cntB, *rpB, *curB, *colB, *incl, *bsum;
    cudaGetSymbolAddress((void**)&h0s, g_h0s);
    cudaGetSymbolAddress((void**)&h1s, g_h1s);
    cudaGetSymbolAddress((void**)&h0t, g_h0t);
    cudaGetSymbolAddress((void**)&h1t, g_h1t);
    cudaGetSymbolAddress((void**)&teach0, g_teach0);
    cudaGetSymbolAddress((void**)&teach1, g_teach1);
    cudaGetSymbolAddress((void**)&pred0, g_pred0);
    cudaGetSymbolAddress((void**)&pred1, g_pred1);
    cudaGetSymbolAddress((void**)&ahi, g_ahi);
    cudaGetSymbolAddress((void**)&alo, g_alo);
    cudaGetSymbolAddress((void**)&qhi, g_qhi);
    cudaGetSymbolAddress((void**)&qlo, g_qlo);
    cudaGetSymbolAddress((void**)&thi, g_thi);
    cudaGetSymbolAddress((void**)&tlo, g_tlo);
    cudaGetSymbolAddress((void**)&wthi, g_wthi);
    cudaGetSymbolAddress((void**)&wtlo, g_wtlo);
    cudaGetSymbolAddress((void**)&cntB, g_cnt);
    cudaGetSymbolAddress((void**)&dinvB, g_dinv);
    cudaGetSymbolAddress((void**)&rpB, g_rowptr);
    cudaGetSymbolAddress((void**)&curB, g_cursor);
    cudaGetSymbolAddress((void**)&colB, g_col);
    cudaGetSymbolAddress((void**)&wgtB, g_wgt);
    cudaGetSymbolAddress((void**)&incl, g_scan_incl);
    cudaGetSymbolAddress((void**)&bsum, g_scan_bsum);
    cudaGetSymbolAddress((void**)&psum, g_psum);
    cudaGetSymbolAddress((void**)&psq, g_psq);
    cudaGetSymbolAddress((void**)&scale, g_scale);
    cudaGetSymbolAddress((void**)&shift, g_shift);
    cudaGetSymbolAddress((void**)&losspart, g_losspart);

    // --- build CSR for both views ---
    for (int v = 0; v < 2; v++) {
        const int* ei = v ? ei2 : ei1;
        int* cnt = cntB + v * NN;
        float* dinv = dinvB + v * NN;
        int* rp = rpB + v * (NN + 1);
        int* cur = curB + v * NN;
        int* col = colB + v * ENN;
        float* wgt = wgtB + v * ENN;
        k_init_cnt<<<NB_BN, 256>>>(cnt);
        k_count<<<(EE + 255) / 256, 256>>>(ei, cnt);
        k_dinv<<<NB_BN, 256>>>(cnt, dinv);
        k_scan_block<<<NB_SCAN, 1024>>>(cnt, incl, bsum);
        k_scan_sums<<<1, 32>>>(bsum);
        k_finalize_rowptr<<<NB_BN, 256>>>(cnt, incl, bsum, rp, cur);
        k_fill<<<(ENN + 255) / 256, 256>>>(ei, dinv, cur, col, wgt);
    }

    auto bn = [&](const float* x, const float* g, const float* be) {
        k_bn_stats<<<NB_BN, 256>>>(x, psum, psq);
        k_bn_fin<<<1, 128>>>(psum, psq, g, be, scale, shift);
    };

    auto run_view = [&](const float* x, int view, float* out_s, float* teach, float* pred) {
        const int* rp = rpB + view * (NN + 1);
        const int* col = colB + view * ENN;
        const float* wgt = wgtB + view * ENN;
        // ---- layer 1: batched student+teacher GEMM ----
        k_prep_a<<<(NN * 256 / 4 + 255) / 256, 256>>>(x, ahi, alo, NN * 256 / 4);
        k_prep_w<<<128, 256>>>(sp[0], wthi, wtlo, 256, 128);
        k_prep_w<<<128, 256>>>(tp[0], wthi + 32768, wtlo + 32768, 256, 128);
        k_bf_gemm<<<dim3(GX, 2), 256>>>(ahi, alo, wthi, wtlo, nullptr, nullptr,
                                        h0s, h0t, nullptr, nullptr, NN, 256, 256);
        k_prop<<<12500, 256>>>(rp, col, wgt, h0s, sp[1], h1s);
        k_prop<<<12500, 256>>>(rp, col, wgt, h0t, tp[1], h1t);
        bn(h1s, sp[2], sp[3]);
        k_bn_apply<<<12500, 256>>>(h1s, scale, shift, sp[4], nullptr, ahi, alo);
        bn(h1t, tp[2], tp[3]);
        k_bn_apply<<<12500, 256>>>(h1t, scale, shift, tp[4], nullptr, thi, tlo);
        // ---- layer 2 ----
        k_prep_w<<<64, 256>>>(sp[5], wthi, wtlo, 128, 128);
        k_bf_gemm<<<dim3(GX, 1), 256>>>(ahi, alo, wthi, wtlo, nullptr, nullptr,
                                        h0s, nullptr, nullptr, nullptr, NN, 128, 128);
        k_prep_w<<<64, 256>>>(tp[5], wthi, wtlo, 128, 128);
        k_bf_gemm<<<dim3(GX, 1), 256>>>(thi, tlo, wthi, wtlo, nullptr, nullptr,
                                        h0t, nullptr, nullptr, nullptr, NN, 128, 128);
        k_prop<<<12500, 256>>>(rp, col, wgt, h0s, sp[6], h1s);
        k_prop<<<12500, 256>>>(rp, col, wgt, h0t, tp[6], h1t);
        bn(h1s, sp[7], sp[8]);
        k_bn_apply<<<12500, 256>>>(h1s, scale, shift, sp[9], out_s, ahi, alo);
        bn(h1t, tp[7], tp[8]);
        k_bn_apply<<<12500, 256>>>(h1t, scale, shift, tp[9], teach, nullptr, nullptr);
        // ---- predictor on student output ----
        k_prep_w<<<256, 256>>>(pW1, wthi, wtlo, 128, 512);
        k_bf_gemm<<<dim3(GX, 4), 256>>>(ahi, alo, wthi, wtlo, pb1, pa,
                                        nullptr, nullptr, qhi, qlo, NN, 128, 512);
        k_prep_w<<<256, 256>>>(pW2, wthi, wtlo, 512, 128);
        k_bf_gemm<<<dim3(GX, 1), 256>>>(qhi, qlo, wthi, wtlo, pb2, nullptr,
                                        pred, nullptr, nullptr, nullptr, NN, 512, 128);
    };

    run_view(x1, 0, out, teach0, pred0);
    run_view(x2, 1, out + (size_t)NN * 128, teach1, pred1);

    // --- loss ---
    k_loss<<<NB_LOSS, 256>>>((const float4*)pred0, (const float4*)teach1,
                             (const float4*)pred1, (const float4*)teach0, losspart);
    k_loss_fin<<<1, 256>>>(losspart, out + (size_t)2 * NN * 128);
}

// round 14
// speedup vs baseline: 1.0255x; 1.0255x over previous
#include <cuda_runtime.h>
#include <cuda_bf16.h>
#include <math.h>
#include <stdint.h>

#define NN 100000
#define EE 1600000
#define ENN (EE + NN)
#define NB_BN 391      /* ceil(NN/256) */
#define NB_LOSS 12500
#define NB_SCAN 98
#define GX 782         /* ceil(NN/128) */

/* weight buffer offsets (bf16 elements) */
#define W_SW1 0
#define W_TW1 32768
#define W_SW2 65536
#define W_TW2 81920
#define W_PW1 98304
#define W_PW2 163840
#define W_TOT 229376

// ---------------- static scratch ----------------
__device__ float g_h0[NN * 128];
__device__ float g_h1[NN * 128];
__device__ float g_teach0[NN * 128];
__device__ float g_teach1[NN * 128];
__device__ float g_pred0[NN * 128];
__device__ float g_pred1[NN * 128];
__device__ float g_q[(size_t)NN * 512];

__device__ __nv_bfloat16 g_wthi[W_TOT];
__device__ __nv_bfloat16 g_wtlo[W_TOT];

__device__ int   g_cnt[2 * NN];
__device__ float g_dinv[2 * NN];
__device__ int   g_rowptr[2 * (NN + 1)];
__device__ int   g_cursor[2 * NN];
__device__ int   g_col[2 * ENN];
__device__ float g_wgt[2 * ENN];
__device__ int   g_scan_incl[NN];
__device__ int   g_scan_bsum[NB_SCAN];

__device__ float g_psum[NB_BN * 128];
__device__ float g_psq[NB_BN * 128];
__device__ float g_scale[128];
__device__ float g_shift[128];
__device__ float g_losspart[NB_LOSS];

// ---------------- bf16 mma helper ----------------
__device__ __forceinline__ void mma_bf16(float* c, const uint32_t* a, const uint32_t* b) {
    asm volatile(
        "mma.sync.aligned.m16n8k16.row.col.f32.bf16.bf16.f32 "
        "{%0,%1,%2,%3},{%4,%5,%6,%7},{%8,%9},{%0,%1,%2,%3};"
        : "+f"(c[0]), "+f"(c[1]), "+f"(c[2]), "+f"(c[3])
        : "r"(a[0]), "r"(a[1]), "r"(a[2]), "r"(a[3]), "r"(b[0]), "r"(b[1]));
}

// ---------------- weight prep: W[K,Mt] fp32 -> Wt_hi/Wt_lo [Mt][K] bf16 ----------------
__global__ void k_prep_w(const float* __restrict__ W, __nv_bfloat16* __restrict__ Wh,
                         __nv_bfloat16* __restrict__ Wl, int K, int Mt) {
    int idx = blockIdx.x * 256 + threadIdx.x;
    if (idx >= K * Mt) return;
    int m = idx / K, k = idx - m * K;
    float v = W[(size_t)k * Mt + m];
    __nv_bfloat16 h = __float2bfloat16(v);
    Wh[idx] = h;
    Wl[idx] = __float2bfloat16(v - __bfloat162float(h));
}

// ---------------- bf16-split tensor GEMM (round-6 layout) ----------------
// C[n,Mt] = f(A)[n,K] @ W[K,Mt] (+bias, +prelu). CTA 128x128, 8 warps (2m x 4n),
// warp tile 64x32, K chunked by 32 (bf16), hi/lo split, 3-term MMA.
// Optional A-affine: f(A) = prelu(A*aSc + aSh, aPa) applied during staging.
#define KC 32
#define STR 36 /* halfs per smem row */

__global__ __launch_bounds__(256) void k_bf_gemm(
    const float* __restrict__ A, const __nv_bfloat16* __restrict__ Wh,
    const __nv_bfloat16* __restrict__ Wl,
    const float* __restrict__ aSc, const float* __restrict__ aSh,
    const float* __restrict__ aPa,
    const float* __restrict__ bias, const float* __restrict__ aprelu,
    float* __restrict__ C, int n, int K, int Mt) {
    __shared__ __nv_bfloat16 smh[4 * 128 * STR];
    __nv_bfloat16* Ah = smh;
    __nv_bfloat16* Al = Ah + 128 * STR;
    __nv_bfloat16* Bh = Al + 128 * STR;
    __nv_bfloat16* Bl = Bh + 128 * STR;

    const int tid = threadIdx.x, lane = tid & 31, wid = tid >> 5;
    const int wm = wid & 1, wn = wid >> 1;
    const int bm = blockIdx.x * 128, bn = blockIdx.y * 128;
    const int lg = lane >> 2, lt = lane & 3;

    float acc[4][4][4];
#pragma unroll
    for (int i = 0; i < 4; i++)
#pragma unroll
        for (int j = 0; j < 4; j++)
#pragma unroll
            for (int k = 0; k < 4; k++) acc[i][j][k] = 0.f;

    const int srow = tid >> 1;          // 0..127
    const int sks = (tid & 1) * 16;     // half of the 32-k chunk
    const float apa = aPa ? __ldg(aPa) : 0.f;

    for (int k0 = 0; k0 < K; k0 += KC) {
        // ---- stage A [128][32] fp32 -> hi/lo bf16 (optional affine+prelu) ----
        {
            int gr = bm + srow;
            __nv_bfloat16 hv[16], lv[16];
#pragma unroll
            for (int q = 0; q < 4; q++) {
                float4 v = make_float4(0.f, 0.f, 0.f, 0.f);
                if (gr < n) v = *(const float4*)(A + (size_t)gr * K + k0 + sks + q * 4);
                if (aSc) {
                    int c = k0 + sks + q * 4;
                    float4 sc = *(const float4*)(aSc + c);
                    float4 sh = *(const float4*)(aSh + c);
                    v.x = fmaf(v.x, sc.x, sh.x); v.y = fmaf(v.y, sc.y, sh.y);
                    v.z = fmaf(v.z, sc.z, sh.z); v.w = fmaf(v.w, sc.w, sh.w);
                    v.x = v.x >= 0.f ? v.x : apa * v.x;
                    v.y = v.y >= 0.f ? v.y : apa * v.y;
                    v.z = v.z >= 0.f ? v.z : apa * v.z;
                    v.w = v.w >= 0.f ? v.w : apa * v.w;
                }
                float vs[4] = {v.x, v.y, v.z, v.w};
#pragma unroll
                for (int e = 0; e < 4; e++) {
                    __nv_bfloat16 h = __float2bfloat16(vs[e]);
                    hv[q * 4 + e] = h;
                    lv[q * 4 + e] = __float2bfloat16(vs[e] - __bfloat162float(h));
                }
            }
            uint2* dh = (uint2*)&Ah[srow * STR + sks];
            uint2* dl = (uint2*)&Al[srow * STR + sks];
#pragma unroll
            for (int q = 0; q < 4; q++) {
                dh[q] = ((uint2*)hv)[q];
                dl[q] = ((uint2*)lv)[q];
            }
        }
        // ---- stage B [128 n][32 k] from Wt hi/lo (already [Mt][K] bf16) ----
        {
            const __nv_bfloat16* sh = Wh + (size_t)(bn + srow) * K + k0 + sks;
            const __nv_bfloat16* sl = Wl + (size_t)(bn + srow) * K + k0 + sks;
            uint2* dh = (uint2*)&Bh[srow * STR + sks];
            uint2* dl = (uint2*)&Bl[srow * STR + sks];
#pragma unroll
            for (int q = 0; q < 4; q++) {
                dh[q] = ((const uint2*)sh)[q];
                dl[q] = ((const uint2*)sl)[q];
            }
        }
        __syncthreads();
#pragma unroll
        for (int kk = 0; kk < KC; kk += 16) {
            uint32_t ah[4][4], al[4][4], bh[4][2], bl[4][2];
            const int kb = kk + lt * 2;
#pragma unroll
            for (int mf = 0; mf < 4; mf++) {
                int r = wm * 64 + mf * 16 + lg;
                ah[mf][0] = *(const uint32_t*)&Ah[r * STR + kb];
                ah[mf][1] = *(const uint32_t*)&Ah[(r + 8) * STR + kb];
                ah[mf][2] = *(const uint32_t*)&Ah[r * STR + kb + 8];
                ah[mf][3] = *(const uint32_t*)&Ah[(r + 8) * STR + kb + 8];
                al[mf][0] = *(const uint32_t*)&Al[r * STR + kb];
                al[mf][1] = *(const uint32_t*)&Al[(r + 8) * STR + kb];
                al[mf][2] = *(const uint32_t*)&Al[r * STR + kb + 8];
                al[mf][3] = *(const uint32_t*)&Al[(r + 8) * STR + kb + 8];
            }
#pragma unroll
            for (int nf = 0; nf < 4; nf++) {
                int c = wn * 32 + nf * 8 + lg;
                bh[nf][0] = *(const uint32_t*)&Bh[c * STR + kb];
                bh[nf][1] = *(const uint32_t*)&Bh[c * STR + kb + 8];
                bl[nf][0] = *(const uint32_t*)&Bl[c * STR + kb];
                bl[nf][1] = *(const uint32_t*)&Bl[c * STR + kb + 8];
            }
#pragma unroll
            for (int mf = 0; mf < 4; mf++)
#pragma unroll
                for (int nf = 0; nf < 4; nf++) {
                    mma_bf16(acc[mf][nf], ah[mf], bh[nf]);
                    mma_bf16(acc[mf][nf], ah[mf], bl[nf]);
                    mma_bf16(acc[mf][nf], al[mf], bh[nf]);
                }
        }
        __syncthreads();
    }

    // epilogue (fragment layout: c0,c1 row lg / c2,c3 row lg+8, cols lt*2,+1)
    float alv = aprelu ? __ldg(aprelu) : 0.f;
#pragma unroll
    for (int mf = 0; mf < 4; mf++) {
        int r0 = bm + wm * 64 + mf * 16 + lg;
#pragma unroll
        for (int nf = 0; nf < 4; nf++) {
            int gc = bn + wn * 32 + nf * 8 + lt * 2;
            float2 v0 = make_float2(acc[mf][nf][0], acc[mf][nf][1]);
            float2 v1 = make_float2(acc[mf][nf][2], acc[mf][nf][3]);
            if (bias) {
                float b0 = __ldg(&bias[gc]), b1 = __ldg(&bias[gc + 1]);
                v0.x += b0; v0.y += b1; v1.x += b0; v1.y += b1;
            }
            if (aprelu) {
                v0.x = v0.x >= 0.f ? v0.x : alv * v0.x;
                v0.y = v0.y >= 0.f ? v0.y : alv * v0.y;
                v1.x = v1.x >= 0.f ? v1.x : alv * v1.x;
                v1.y = v1.y >= 0.f ? v1.y : alv * v1.y;
            }
            if (r0 < n) *(float2*)(C + (size_t)r0 * Mt + gc) = v0;
            if (r0 + 8 < n) *(float2*)(C + (size_t)(r0 + 8) * Mt + gc) = v1;
        }
    }
}

// ---------------- CSR build ----------------
__global__ void k_init_cnt(int* cnt) {
    int i = blockIdx.x * 256 + threadIdx.x;
    if (i < NN) cnt[i] = 1;
}
__global__ void k_count(const int* __restrict__ ei, int* cnt) {
    int e = blockIdx.x * 256 + threadIdx.x;
    if (e < EE) atomicAdd(&cnt[ei[EE + e]], 1);
}
__global__ void k_dinv(const int* __restrict__ cnt, float* dinv) {
    int i = blockIdx.x * 256 + threadIdx.x;
    if (i < NN) dinv[i] = rsqrtf((float)cnt[i]);
}
__global__ void k_scan_block(const int* __restrict__ cnt, int* incl, int* bsum) {
    __shared__ int sm[1024];
    int i = blockIdx.x * 1024 + threadIdx.x;
    int v = (i < NN) ? cnt[i] : 0;
    sm[threadIdx.x] = v;
    __syncthreads();
    for (int off = 1; off < 1024; off <<= 1) {
        int t = (threadIdx.x >= off) ? sm[threadIdx.x - off] : 0;
        __syncthreads();
        sm[threadIdx.x] += t;
        __syncthreads();
    }
    if (i < NN) incl[i] = sm[threadIdx.x];
    if (threadIdx.x == 1023) bsum[blockIdx.x] = sm[1023];
}
__global__ void k_scan_sums(int* bsum) {
    if (threadIdx.x == 0 && blockIdx.x == 0) {
        int acc = 0;
        for (int b = 0; b < NB_SCAN; b++) { int t = bsum[b]; bsum[b] = acc; acc += t; }
    }
}
__global__ void k_finalize_rowptr(const int* __restrict__ cnt, const int* __restrict__ incl,
                                  const int* __restrict__ bsum, int* rowptr, int* cursor) {
    int i = blockIdx.x * 256 + threadIdx.x;
    if (i < NN) {
        int inclg = incl[i] + bsum[i >> 10];
        int excl = inclg - cnt[i];
        rowptr[i] = excl;
        cursor[i] = excl;
        if (i == NN - 1) rowptr[NN] = inclg;
    }
}
__global__ void k_fill(const int* __restrict__ ei, const float* __restrict__ dinv,
                       int* cursor, int* col, float* wgt) {
    int t = blockIdx.x * 256 + threadIdx.x;
    if (t < EE) {
        int s = ei[t], d = ei[EE + t];
        int p = atomicAdd(&cursor[d], 1);
        col[p] = s;
        wgt[p] = dinv[s] * dinv[d];
    } else if (t < ENN) {
        int i = t - EE;
        int p = atomicAdd(&cursor[i], 1);
        col[p] = i;
        wgt[p] = dinv[i] * dinv[i];
    }
}

// ---------------- propagate ----------------
__global__ __launch_bounds__(256) void k_prop(const int* __restrict__ rowptr,
                                              const int* __restrict__ col,
                                              const float* __restrict__ wgt,
                                              const float* __restrict__ h,
                                              const float* __restrict__ bias,
                                              float* __restrict__ out) {
    int w = (blockIdx.x * 256 + threadIdx.x) >> 5;
    int lane = threadIdx.x & 31;
    if (w >= NN) return;
    int beg = rowptr[w], end = rowptr[w + 1];
    float4 acc = make_float4(0.f, 0.f, 0.f, 0.f);
    const float4* H = (const float4*)h;
    for (int e = beg; e < end; e++) {
        int s = __ldg(&col[e]);
        float wv = __ldg(&wgt[e]);
        float4 v = __ldg(&H[(size_t)s * 32 + lane]);
        acc.x = fmaf(wv, v.x, acc.x);
        acc.y = fmaf(wv, v.y, acc.y);
        acc.z = fmaf(wv, v.z, acc.z);
        acc.w = fmaf(wv, v.w, acc.w);
    }
    float4 b = ((const float4*)bias)[lane];
    acc.x += b.x; acc.y += b.y; acc.z += b.z; acc.w += b.w;
    ((float4*)out)[(size_t)w * 32 + lane] = acc;
}

// ---------------- BN ----------------
__global__ __launch_bounds__(256) void k_bn_stats(const float* __restrict__ x,
                                                  float* __restrict__ psum,
                                                  float* __restrict__ psq) {
    __shared__ float4 smS[256], smQ[256];
    int t = threadIdx.x;
    int cg = t & 31, rr = t >> 5;
    int rowStart = blockIdx.x * 256;
    int rowEnd = rowStart + 256; if (rowEnd > NN) rowEnd = NN;
    float4 s = make_float4(0.f, 0.f, 0.f, 0.f), q = s;
    const float4* X = (const float4*)x;
    for (int r = rowStart + rr; r < rowEnd; r += 8) {
        float4 v = X[(size_t)r * 32 + cg];
        s.x += v.x; s.y += v.y; s.z += v.z; s.w += v.w;
        q.x = fmaf(v.x, v.x, q.x); q.y = fmaf(v.y, v.y, q.y);
        q.z = fmaf(v.z, v.z, q.z); q.w = fmaf(v.w, v.w, q.w);
    }
    smS[t] = s; smQ[t] = q;
    __syncthreads();
    if (rr == 0) {
        for (int k = 1; k < 8; k++) {
            float4 a = smS[k * 32 + cg], b = smQ[k * 32 + cg];
            s.x += a.x; s.y += a.y; s.z += a.z; s.w += a.w;
            q.x += b.x; q.y += b.y; q.z += b.z; q.w += b.w;
        }
        ((float4*)psum)[blockIdx.x * 32 + cg] = s;
        ((float4*)psq)[blockIdx.x * 32 + cg] = q;
    }
}
__global__ void k_bn_fin(const float* __restrict__ psum, const float* __restrict__ psq,
                         const float* __restrict__ g, const float* __restrict__ be,
                         float* scale, float* shift) {
    int c = threadIdx.x;
    float s = 0.f, q = 0.f;
    for (int b = 0; b < NB_BN; b++) { s += psum[b * 128 + c]; q += psq[b * 128 + c]; }
    float mu = s / (float)NN;
    float var = q / (float)NN - mu * mu;
    var = fmaxf(var, 0.f);
    float inv = rsqrtf(var + 1e-5f);
    float sc = g[c] * inv;
    scale[c] = sc;
    shift[c] = be[c] - mu * sc;
}
__global__ __launch_bounds__(256) void k_bn_apply(const float* __restrict__ x,
                                                  const float* __restrict__ scale,
                                                  const float* __restrict__ shift,
                                                  const float* __restrict__ aptr,
                                                  float* __restrict__ out) {
    int i = blockIdx.x * 256 + threadIdx.x;
    if (i >= NN * 32) return;
    int cg = i & 31;
    float a = *aptr;
    float4 v = ((const float4*)x)[i];
    float4 sc = ((const float4*)scale)[cg];
    float4 sh = ((const float4*)shift)[cg];
    v.x = fmaf(v.x, sc.x, sh.x); v.y = fmaf(v.y, sc.y, sh.y);
    v.z = fmaf(v.z, sc.z, sh.z); v.w = fmaf(v.w, sc.w, sh.w);
    v.x = v.x >= 0.f ? v.x : a * v.x;
    v.y = v.y >= 0.f ? v.y : a * v.y;
    v.z = v.z >= 0.f ? v.z : a * v.z;
    v.w = v.w >= 0.f ? v.w : a * v.w;
    ((float4*)out)[i] = v;
}

// ---------------- loss ----------------
__global__ __launch_bounds__(256) void k_loss(const float4* __restrict__ p1,
                                              const float4* __restrict__ t2,
                                              const float4* __restrict__ p2,
                                              const float4* __restrict__ t1,
                                              float* __restrict__ part) {
    int w = (blockIdx.x * 256 + threadIdx.x) >> 5;
    int lane = threadIdx.x & 31;
    float contrib = 0.f;
    if (w < NN) {
        float4 a = p1[(size_t)w * 32 + lane];
        float4 b = t2[(size_t)w * 32 + lane];
        float4 c = p2[(size_t)w * 32 + lane];
        float4 d = t1[(size_t)w * 32 + lane];
        float dab = a.x * b.x + a.y * b.y + a.z * b.z + a.w * b.w;
        float naa = a.x * a.x + a.y * a.y + a.z * a.z + a.w * a.w;
        float nbb = b.x * b.x + b.y * b.y + b.z * b.z + b.w * b.w;
        float dcd = c.x * d.x + c.y * d.y + c.z * d.z + c.w * d.w;
        float ncc = c.x * c.x + c.y * c.y + c.z * c.z + c.w * c.w;
        float ndd = d.x * d.x + d.y * d.y + d.z * d.z + d.w * d.w;
        for (int off = 16; off; off >>= 1) {
            dab += __shfl_xor_sync(0xffffffffu, dab, off);
            naa += __shfl_xor_sync(0xffffffffu, naa, off);
            nbb += __shfl_xor_sync(0xffffffffu, nbb, off);
            dcd += __shfl_xor_sync(0xffffffffu, dcd, off);
            ncc += __shfl_xor_sync(0xffffffffu, ncc, off);
            ndd += __shfl_xor_sync(0xffffffffu, ndd, off);
        }
        if (lane == 0) {
            float c1 = dab / (fmaxf(sqrtf(naa), 1e-12f) * fmaxf(sqrtf(nbb), 1e-12f));
            float c2 = dcd / (fmaxf(sqrtf(ncc), 1e-12f) * fmaxf(sqrtf(ndd), 1e-12f));
            contrib = 4.f - 2.f * c1 - 2.f * c2;
        }
    }
    __shared__ float sm[8];
    int wl = threadIdx.x >> 5;
    if (lane == 0) sm[wl] = contrib;
    __syncthreads();
    if (threadIdx.x == 0) {
        float s = 0.f;
        for (int i = 0; i < 8; i++) s += sm[i];
        part[blockIdx.x] = s;
    }
}
__global__ void k_loss_fin(const float* __restrict__ part, float* __restrict__ outp) {
    __shared__ float sm[256];
    float s = 0.f;
    for (int i = threadIdx.x; i < NB_LOSS; i += 256) s += part[i];
    sm[threadIdx.x] = s;
    __syncthreads();
    for (int off = 128; off; off >>= 1) {
        if (threadIdx.x < off) sm[threadIdx.x] += sm[threadIdx.x + off];
        __syncthreads();
    }
    if (threadIdx.x == 0) outp[0] = sm[0] / (float)NN;
}

// ---------------- host orchestration ----------------
extern "C" void kernel_launch(void* const* d_in, const int* in_sizes, int n_in,
                              void* d_out, int out_size) {
    (void)in_sizes; (void)n_in; (void)out_size;
    const float* x1 = (const float*)d_in[0];
    const float* x2 = (const float*)d_in[1];
    const int* ei1 = (const int*)d_in[2];
    const int* ei2 = (const int*)d_in[3];
    const float* sp[10]; for (int i = 0; i < 10; i++) sp[i] = (const float*)d_in[4 + i];
    const float* tp[10]; for (int i = 0; i < 10; i++) tp[i] = (const float*)d_in[14 + i];
    const float* pW1 = (const float*)d_in[24];
    const float* pb1 = (const float*)d_in[25];
    const float* pa  = (const float*)d_in[26];
    const float* pW2 = (const float*)d_in[27];
    const float* pb2 = (const float*)d_in[28];
    float* out = (float*)d_out;

    float *h0, *h1, *teach0, *teach1, *pred0, *pred1, *q;
    float *dinvB, *wgtB, *psum, *psq, *scale, *shift, *losspart;
    __nv_bfloat16 *wthi, *wtlo;
    int *cntB, *rpB, *curB, *colB, *incl, *bsum;
    cudaGetSymbolAddress((void**)&h0, g_h0);
    cudaGetSymbolAddress((void**)&h1, g_h1);
    cudaGetSymbolAddress((void**)&teach0, g_teach0);
    cudaGetSymbolAddress((void**)&teach1, g_teach1);
    cudaGetSymbolAddress((void**)&pred0, g_pred0);
    cudaGetSymbolAddress((void**)&pred1, g_pred1);
    cudaGetSymbolAddress((void**)&q, g_q);
    cudaGetSymbolAddress((void**)&wthi, g_wthi);
    cudaGetSymbolAddress((void**)&wtlo, g_wtlo);
    cudaGetSymbolAddress((void**)&cntB, g_cnt);
    cudaGetSymbolAddress((void**)&dinvB, g_dinv);
    cudaGetSymbolAddress((void**)&rpB, g_rowptr);
    cudaGetSymbolAddress((void**)&curB, g_cursor);
    cudaGetSymbolAddress((void**)&colB, g_col);
    cudaGetSymbolAddress((void**)&wgtB, g_wgt);
    cudaGetSymbolAddress((void**)&incl, g_scan_incl);
    cudaGetSymbolAddress((void**)&bsum, g_scan_bsum);
    cudaGetSymbolAddress((void**)&psum, g_psum);
    cudaGetSymbolAddress((void**)&psq, g_psq);
    cudaGetSymbolAddress((void**)&scale, g_scale);
    cudaGetSymbolAddress((void**)&shift, g_shift);
    cudaGetSymbolAddress((void**)&losspart, g_losspart);

    // --- build CSR for both views ---
    for (int v = 0; v < 2; v++) {
        const int* ei = v ? ei2 : ei1;
        int* cnt = cntB + v * NN;
        float* dinv = dinvB + v * NN;
        int* rp = rpB + v * (NN + 1);
        int* cur = curB + v * NN;
        int* col = colB + v * ENN;
        float* wgt = wgtB + v * ENN;
        k_init_cnt<<<NB_BN, 256>>>(cnt);
        k_count<<<(EE + 255) / 256, 256>>>(ei, cnt);
        k_dinv<<<NB_BN, 256>>>(cnt, dinv);
        k_scan_block<<<NB_SCAN, 1024>>>(cnt, incl, bsum);
        k_scan_sums<<<1, 32>>>(bsum);
        k_finalize_rowptr<<<NB_BN, 256>>>(cnt, incl, bsum, rp, cur);
        k_fill<<<(ENN + 255) / 256, 256>>>(ei, dinv, cur, col, wgt);
    }

    // --- prep all weights ONCE ---
    k_prep_w<<<128, 256>>>(sp[0], wthi + W_SW1, wtlo + W_SW1, 256, 128);
    k_prep_w<<<128, 256>>>(tp[0], wthi + W_TW1, wtlo + W_TW1, 256, 128);
    k_prep_w<<<64, 256>>>(sp[5], wthi + W_SW2, wtlo + W_SW2, 128, 128);
    k_prep_w<<<64, 256>>>(tp[5], wthi + W_TW2, wtlo + W_TW2, 128, 128);
    k_prep_w<<<256, 256>>>(pW1, wthi + W_PW1, wtlo + W_PW1, 128, 512);
    k_prep_w<<<256, 256>>>(pW2, wthi + W_PW2, wtlo + W_PW2, 512, 128);

    auto bn = [&](const float* x, const float* g, const float* be) {
        k_bn_stats<<<NB_BN, 256>>>(x, psum, psq);
        k_bn_fin<<<1, 128>>>(psum, psq, g, be, scale, shift);
    };

    // --- 4 encoder runs ---
    auto encoder = [&](const float* x, int view, const float* const* P,
                       int wL1, int wL2, float* outp) {
        const int* rp = rpB + view * (NN + 1);
        const int* col = colB + view * ENN;
        const float* wgt = wgtB + view * ENN;
        // layer 1
        k_bf_gemm<<<dim3(GX, 1), 256>>>(x, wthi + wL1, wtlo + wL1,
                                        nullptr, nullptr, nullptr,
                                        nullptr, nullptr, h0, NN, 256, 128);
        k_prop<<<12500, 256>>>(rp, col, wgt, h0, P[1], h1);
        bn(h1, P[2], P[3]);
        // layer 2 (bn_apply + PReLU fused into A-staging)
        k_bf_gemm<<<dim3(GX, 1), 256>>>(h1, wthi + wL2, wtlo + wL2,
                                        scale, shift, P[4],
                                        nullptr, nullptr, h0, NN, 128, 128);
        k_prop<<<12500, 256>>>(rp, col, wgt, h0, P[6], h1);
        bn(h1, P[7], P[8]);
        k_bn_apply<<<12500, 256>>>(h1, scale, shift, P[9], outp);
    };

    encoder(x1, 0, sp, W_SW1, W_SW2, out);
    encoder(x2, 1, sp, W_SW1, W_SW2, out + (size_t)NN * 128);
    encoder(x1, 0, tp, W_TW1, W_TW2, teach0);
    encoder(x2, 1, tp, W_TW1, W_TW2, teach1);

    // --- predictor MLP on both student outputs ---
    k_bf_gemm<<<dim3(GX, 4), 256>>>(out, wthi + W_PW1, wtlo + W_PW1,
                                    nullptr, nullptr, nullptr,
                                    pb1, pa, q, NN, 128, 512);
    k_bf_gemm<<<dim3(GX, 1), 256>>>(q, wthi + W_PW2, wtlo + W_PW2,
                                    nullptr, nullptr, nullptr,
                                    pb2, nullptr, pred0, NN, 512, 128);
    k_bf_gemm<<<dim3(GX, 4), 256>>>(out + (size_t)NN * 128, wthi + W_PW1, wtlo + W_PW1,
                                    nullptr, nullptr, nullptr,
                                    pb1, pa, q, NN, 128, 512);
    k_bf_gemm<<<dim3(GX, 1), 256>>>(q, wthi + W_PW2, wtlo + W_PW2,
                                    nullptr, nullptr, nullptr,
                                    pb2, nullptr, pred1, NN, 512, 128);

    // --- loss ---
    k_loss<<<NB_LOSS, 256>>>((const float4*)pred0, (const float4*)teach1,
                             (const float4*)pred1, (const float4*)teach0, losspart);
    k_loss_fin<<<1, 256>>>(losspart, out + (size_t)2 * NN * 128);
}